// round 5
// baseline (speedup 1.0000x reference)
#include <cuda_runtime.h>
#include <cuda_bf16.h>

#define NFD 32
#define NOD 128
#define PST 129           // padded smem stride (odd -> conflict-free column gather)
#define WPB 8             // warps per block
#define BT (WPB * 32)

static __device__ __forceinline__ float comp(const float4 v, int c) {
    switch (c & 3) {
        case 0:  return v.x;
        case 1:  return v.y;
        case 2:  return v.z;
        default: return v.w;
    }
}

__global__ __launch_bounds__(BT, 4)
void slater_det_kernel(const int* __restrict__ n,
                       const float* __restrict__ Phi,
                       float* __restrict__ out,
                       int nsamples)
{
    __shared__ float Phi_sh[NFD * PST];
    __shared__ __align__(16) int    idx_sh[WPB][NFD];
    __shared__ __align__(16) float4 piv_sh[WPB][2][8];   // double-buffered pivot row

    const int tid  = threadIdx.x;
    const int lane = tid & 31;
    const int wid  = tid >> 5;

    // Stage Phi (32x128 fp32 = 16KB) into padded shared memory once per block.
    for (int t = tid; t < NFD * NOD; t += BT) {
        int i = t >> 7;
        int c = t & 127;
        Phi_sh[i * PST + c] = Phi[t];
    }
    __syncthreads();

    const unsigned FULL = 0xffffffffu;
    const int warps_total = (gridDim.x * BT) >> 5;
    int gw = (blockIdx.x * BT + tid) >> 5;

    for (int s = gw; s < nsamples; s += warps_total) {
        // ---- Build idx: ranks of the 32 occupied orbitals (ascending) ----
        const int4 v = ((const int4*)(n + (size_t)s * NOD))[lane];
        unsigned m4 = (unsigned)(v.x != 0)
                    | ((unsigned)(v.y != 0) << 1)
                    | ((unsigned)(v.z != 0) << 2)
                    | ((unsigned)(v.w != 0) << 3);
        unsigned b0 = __ballot_sync(FULL, v.x != 0);
        unsigned b1 = __ballot_sync(FULL, v.y != 0);
        unsigned b2 = __ballot_sync(FULL, v.z != 0);
        unsigned b3 = __ballot_sync(FULL, v.w != 0);
        unsigned lowmask = (1u << lane) - 1u;
        int base = __popc(b0 & lowmask) + __popc(b1 & lowmask)
                 + __popc(b2 & lowmask) + __popc(b3 & lowmask);

        int r0 = base;
        if (m4 & 1u) idx_sh[wid][r0] = lane * 4 + 0;
        int r1 = r0 + (int)(m4 & 1u);
        if (m4 & 2u) idx_sh[wid][r1] = lane * 4 + 1;
        int r2 = r1 + (int)((m4 >> 1) & 1u);
        if (m4 & 4u) idx_sh[wid][r2] = lane * 4 + 2;
        int r3 = r2 + (int)((m4 >> 2) & 1u);
        if (m4 & 8u) idx_sh[wid][r3] = lane * 4 + 3;
        __syncwarp();

        // ---- Gather: lane i holds row i as 8 float4 quads ----
        float4 rv[8];
        #pragma unroll
        for (int q = 0; q < 8; q++) {
            int4 c4 = ((const int4*)idx_sh[wid])[q];   // broadcast LDS.128
            float4 t;
            t.x = Phi_sh[lane * PST + c4.x];           // conflict-free (stride 129)
            t.y = Phi_sh[lane * PST + c4.y];
            t.z = Phi_sh[lane * PST + c4.z];
            t.w = Phi_sh[lane * PST + c4.w];
            rv[q] = t;
        }
        // (no syncwarp needed here: the in-loop syncwarps below order these
        //  idx_sh reads before any next-iteration writes)

        // ---- LU with partial pivoting; pivot row broadcast via smem ----
        unsigned active = FULL;
        float det = 1.0f;
        int inv_cnt = 0;

        #pragma unroll
        for (int k = 0; k < NFD; k++) {
            const int kq = k >> 2;
            float elemk = comp(rv[kq], k);

            // argmax |elemk| over active lanes via REDUX.MAX on packed key
            float av = fabsf(elemk);
            unsigned key = (active & (1u << lane))
                         ? ((__float_as_uint(av) & 0xffffffe0u) | (unsigned)lane)
                         : 0u;
            unsigned mx = __reduce_max_sync(FULL, key);
            int p = (int)(mx & 31u);

            inv_cnt += __popc(active & ((1u << p) - 1u));
            active &= ~(1u << p);

            // Pivot lane publishes its remaining row quads (STS.128)
            if (lane == p) {
                #pragma unroll
                for (int q = kq; q < 8; q++)
                    piv_sh[wid][k & 1][q] = rv[q];
            }
            __syncwarp();

            // All lanes: pivot value + rank-1 update from broadcast LDS.128
            float4 pq  = piv_sh[wid][k & 1][kq];
            float  piv = comp(pq, k);
            det *= piv;
            float f = elemk * ((piv != 0.0f) ? __frcp_rn(piv) : 0.0f);
            // No masking of f: retired rows (incl. the pivot row) receive
            // harmless updates and are never read again; pivot selection is
            // masked by `active`.
            #pragma unroll
            for (int q = kq; q < 8; q++) {
                float4 pv = piv_sh[wid][k & 1][q];
                rv[q].x = fmaf(-f, pv.x, rv[q].x);
                rv[q].y = fmaf(-f, pv.y, rv[q].y);
                rv[q].z = fmaf(-f, pv.z, rv[q].z);
                rv[q].w = fmaf(-f, pv.w, rv[q].w);
            }
        }

        if (lane == 0)
            out[s] = (inv_cnt & 1) ? -det : det;
    }
}

extern "C" void kernel_launch(void* const* d_in, const int* in_sizes, int n_in,
                              void* d_out, int out_size)
{
    const int*   n_ptr = (const int*)d_in[0];      // n:   (B, 128) int32
    const float* Phi   = (const float*)d_in[1];    // Phi: (32, 128) float32
    float*       out   = (float*)d_out;            // det: (B,) float32

    int nsamples = in_sizes[0] / NOD;              // B = 131072

    // 148 SMs x 4 resident blocks (reg-capped), grid-stride over samples.
    int grid = 148 * 4;
    slater_det_kernel<<<grid, BT>>>(n_ptr, Phi, out, nsamples);
}

// round 6
// speedup vs baseline: 1.1087x; 1.1087x over previous
#include <cuda_runtime.h>
#include <cuda_bf16.h>

#define NFD 32
#define NOD 128
#define PST 129           // padded smem stride (odd -> conflict-free column gather)
#define WPB 8             // warps per block
#define BT (WPB * 32)
#define PIV_THRESH 1e-4f  // min |pivot| below which we redo with partial pivoting

__global__ __launch_bounds__(BT, 4)
void slater_det_kernel(const int* __restrict__ n,
                       const float* __restrict__ Phi,
                       float* __restrict__ out,
                       int nsamples)
{
    __shared__ float Phi_sh[NFD * PST];
    __shared__ int   idx_sh[WPB][NFD];

    const int tid  = threadIdx.x;
    const int lane = tid & 31;
    const int wid  = tid >> 5;

    // Stage Phi (32x128 fp32 = 16KB) into padded shared memory once per block.
    for (int t = tid; t < NFD * NOD; t += BT) {
        int i = t >> 7;
        int c = t & 127;
        Phi_sh[i * PST + c] = Phi[t];
    }
    __syncthreads();

    const unsigned FULL = 0xffffffffu;
    const int warps_total = (gridDim.x * BT) >> 5;
    int gw = (blockIdx.x * BT + tid) >> 5;

    for (int s = gw; s < nsamples; s += warps_total) {
        // Guard idx_sh reads of the previous iteration against this one's writes.
        __syncwarp();

        // ---- Build idx: ranks of the 32 occupied orbitals (ascending) ----
        const int4 v = ((const int4*)(n + (size_t)s * NOD))[lane];
        unsigned m4 = (unsigned)(v.x != 0)
                    | ((unsigned)(v.y != 0) << 1)
                    | ((unsigned)(v.z != 0) << 2)
                    | ((unsigned)(v.w != 0) << 3);
        unsigned b0 = __ballot_sync(FULL, v.x != 0);
        unsigned b1 = __ballot_sync(FULL, v.y != 0);
        unsigned b2 = __ballot_sync(FULL, v.z != 0);
        unsigned b3 = __ballot_sync(FULL, v.w != 0);
        unsigned lowmask = (1u << lane) - 1u;
        int base = __popc(b0 & lowmask) + __popc(b1 & lowmask)
                 + __popc(b2 & lowmask) + __popc(b3 & lowmask);

        int r0 = base;
        if (m4 & 1u) idx_sh[wid][r0] = lane * 4 + 0;
        int r1 = r0 + (int)(m4 & 1u);
        if (m4 & 2u) idx_sh[wid][r1] = lane * 4 + 1;
        int r2 = r1 + (int)((m4 >> 1) & 1u);
        if (m4 & 4u) idx_sh[wid][r2] = lane * 4 + 2;
        int r3 = r2 + (int)((m4 >> 2) & 1u);
        if (m4 & 8u) idx_sh[wid][r3] = lane * 4 + 3;
        __syncwarp();

        // ---- Gather: lane i holds row i of the 32x32 matrix in registers ----
        float r[NFD];
        #pragma unroll
        for (int j = 0; j < NFD; j++) {
            int c = idx_sh[wid][j];                 // broadcast LDS
            r[j] = Phi_sh[lane * PST + c];          // conflict-free (stride 129)
        }

        // ---- Fast path: LU WITHOUT pivoting (pivot = diagonal lane k) ----
        // Fixed-lane shfl: no REDUX, no mask bookkeeping, shortest dep chain.
        float det  = 1.0f;
        float minp = 1e30f;

        #pragma unroll
        for (int k = 0; k < NFD; k++) {
            float piv = __shfl_sync(FULL, r[k], k);
            minp = fminf(minp, fabsf(piv));
            det *= piv;
            float invp = __frcp_rn(piv);
            // Only rows below k are updated; rows <= k are frozen (they are
            // pivot rows of earlier/this step and must stay intact).
            float f = (lane > k) ? (r[k] * invp) : 0.0f;
            #pragma unroll
            for (int j = k + 1; j < NFD; j++) {
                float pv = __shfl_sync(FULL, r[j], k);   // broadcast pivot row
                r[j] = fmaf(-f, pv, r[j]);
            }
        }

        // Warp-uniform check (piv values were broadcast, so minp/det agree).
        bool bad = (minp < PIV_THRESH) || !isfinite(det);

        if (bad) {
            // ---- Rare fallback: re-gather and redo WITH partial pivoting ----
            #pragma unroll
            for (int j = 0; j < NFD; j++) {
                int c = idx_sh[wid][j];
                r[j] = Phi_sh[lane * PST + c];
            }

            unsigned active = FULL;
            det = 1.0f;
            int inv_cnt = 0;

            #pragma unroll
            for (int k = 0; k < NFD; k++) {
                float av = fabsf(r[k]);
                unsigned key = (active & (1u << lane))
                             ? ((__float_as_uint(av) & 0xffffffe0u) | (unsigned)lane)
                             : 0u;
                unsigned mx = __reduce_max_sync(FULL, key);
                int p = (int)(mx & 31u);

                float piv = __shfl_sync(FULL, r[k], p);
                inv_cnt += __popc(active & ((1u << p) - 1u));
                active &= ~(1u << p);

                det *= piv;
                float invp = (piv != 0.0f) ? __frcp_rn(piv) : 0.0f;
                float f = (active & (1u << lane)) ? (r[k] * invp) : 0.0f;

                #pragma unroll
                for (int j = k + 1; j < NFD; j++) {
                    float pv = __shfl_sync(FULL, r[j], p);
                    r[j] = fmaf(-f, pv, r[j]);
                }
            }
            if (inv_cnt & 1) det = -det;
        }

        if (lane == 0)
            out[s] = det;
    }
}

extern "C" void kernel_launch(void* const* d_in, const int* in_sizes, int n_in,
                              void* d_out, int out_size)
{
    const int*   n_ptr = (const int*)d_in[0];      // n:   (B, 128) int32
    const float* Phi   = (const float*)d_in[1];    // Phi: (32, 128) float32
    float*       out   = (float*)d_out;            // det: (B,) float32

    int nsamples = in_sizes[0] / NOD;              // B = 131072

    // 148 SMs x 4 resident blocks (32 warps/SM), grid-stride over samples.
    int grid = 148 * 4;
    slater_det_kernel<<<grid, BT>>>(n_ptr, Phi, out, nsamples);
}

// round 7
// speedup vs baseline: 1.7894x; 1.6140x over previous
#include <cuda_runtime.h>
#include <cuda_bf16.h>

#define NFD 32
#define NOD 128
#define PST 129           // padded smem stride (odd -> conflict-free column gather)
#define WPB 8             // warps per block
#define BT (WPB * 32)
#define PIV_THRESH 1e-4f  // min |pivot| below which we redo with partial pivoting

__global__ __launch_bounds__(BT, 2)
void slater_det_kernel(const int* __restrict__ n,
                       const float* __restrict__ Phi,
                       float* __restrict__ out,
                       int nsamples)
{
    __shared__ float Phi_sh[NFD * PST];
    __shared__ int   idx_sh[WPB][2][NFD];

    const int tid  = threadIdx.x;
    const int lane = tid & 31;
    const int wid  = tid >> 5;
    const int half = lane >> 4;       // 0: sample s0, 1: sample s0+1
    const int l    = lane & 15;       // lane within half

    // Stage Phi (32x128 fp32 = 16KB) into padded shared memory once per block.
    for (int t = tid; t < NFD * NOD; t += BT) {
        int i = t >> 7;
        int c = t & 127;
        Phi_sh[i * PST + c] = Phi[t];
    }
    __syncthreads();

    const unsigned FULL = 0xffffffffu;
    const int warps_total = (gridDim.x * BT) >> 5;
    const int npairs = nsamples >> 1;
    int gw = (blockIdx.x * BT + tid) >> 5;

    for (int p = gw; p < npairs; p += warps_total) {
        int s0 = 2 * p;
        __syncwarp();   // previous iteration's idx_sh reads vs this one's writes

        // ---- Build idx for BOTH samples (full warp per sample) ----
        #pragma unroll
        for (int t = 0; t < 2; t++) {
            const int4 v = ((const int4*)(n + (size_t)(s0 + t) * NOD))[lane];
            unsigned m4 = (unsigned)(v.x != 0)
                        | ((unsigned)(v.y != 0) << 1)
                        | ((unsigned)(v.z != 0) << 2)
                        | ((unsigned)(v.w != 0) << 3);
            unsigned b0 = __ballot_sync(FULL, v.x != 0);
            unsigned b1 = __ballot_sync(FULL, v.y != 0);
            unsigned b2 = __ballot_sync(FULL, v.z != 0);
            unsigned b3 = __ballot_sync(FULL, v.w != 0);
            unsigned lowmask = (1u << lane) - 1u;
            int base = __popc(b0 & lowmask) + __popc(b1 & lowmask)
                     + __popc(b2 & lowmask) + __popc(b3 & lowmask);
            int r0 = base;
            if (m4 & 1u) idx_sh[wid][t][r0] = lane * 4 + 0;
            int r1 = r0 + (int)(m4 & 1u);
            if (m4 & 2u) idx_sh[wid][t][r1] = lane * 4 + 1;
            int r2 = r1 + (int)((m4 >> 1) & 1u);
            if (m4 & 4u) idx_sh[wid][t][r2] = lane * 4 + 2;
            int r3 = r2 + (int)((m4 >> 2) & 1u);
            if (m4 & 8u) idx_sh[wid][t][r3] = lane * 4 + 3;
        }
        __syncwarp();

        // ---- Gather: lane owns rows l and l+16 of its half's sample ----
        float rlo[NFD], rhi[NFD];
        #pragma unroll
        for (int j = 0; j < NFD; j++) {
            int c = idx_sh[wid][half][j];
            rlo[j] = Phi_sh[l * PST + c];
            rhi[j] = Phi_sh[(l + 16) * PST + c];
        }

        // ---- Fast path: pivot-free LU, 2 samples per warp ----
        float det  = 1.0f;
        float minp = 1e30f;

        #pragma unroll
        for (int k = 0; k < NFD; k++) {
            const int src = (k & 15) + (half << 4);   // owner of row k in this half
            float pl = (k < 16) ? rlo[k] : rhi[k];
            float piv = __shfl_sync(FULL, pl, src);
            minp = fminf(minp, fabsf(piv));
            det *= piv;
            float invp = __frcp_rn(piv);

            if (k < 16) {
                float fLo = (l > k) ? (rlo[k] * invp) : 0.0f;
                float fHi = rhi[k] * invp;            // all hi rows are below k
                #pragma unroll
                for (int j = k + 1; j < NFD; j++) {
                    float pv = __shfl_sync(FULL, rlo[j], src);
                    rlo[j] = fmaf(-fLo, pv, rlo[j]);
                    rhi[j] = fmaf(-fHi, pv, rhi[j]);
                }
            } else {
                float fHi = (l + 16 > k) ? (rhi[k] * invp) : 0.0f;
                #pragma unroll
                for (int j = k + 1; j < NFD; j++) {
                    float pv = __shfl_sync(FULL, rhi[j], src);
                    rhi[j] = fmaf(-fHi, pv, rhi[j]);
                }
            }
        }

        // per-half validity (piv broadcast within half -> uniform per half)
        int badme = ((minp < PIV_THRESH) || !isfinite(det)) ? 1 : 0;
        int badA = __shfl_sync(FULL, badme, 0);
        int badB = __shfl_sync(FULL, badme, 16);

        // ---- Rare fallback: redo bad sample with full-warp pivoted LU ----
        #pragma unroll
        for (int t = 0; t < 2; t++) {
            if ((t == 0 ? badA : badB)) {
                float r[NFD];
                #pragma unroll
                for (int j = 0; j < NFD; j++)
                    r[j] = Phi_sh[lane * PST + idx_sh[wid][t][j]];

                unsigned active = FULL;
                float dfb = 1.0f;
                int inv_cnt = 0;
                #pragma unroll
                for (int k = 0; k < NFD; k++) {
                    float av = fabsf(r[k]);
                    unsigned key = (active & (1u << lane))
                                 ? ((__float_as_uint(av) & 0xffffffe0u) | (unsigned)lane)
                                 : 0u;
                    unsigned mx = __reduce_max_sync(FULL, key);
                    int pp = (int)(mx & 31u);
                    float piv = __shfl_sync(FULL, r[k], pp);
                    inv_cnt += __popc(active & ((1u << pp) - 1u));
                    active &= ~(1u << pp);
                    dfb *= piv;
                    float invp = (piv != 0.0f) ? __frcp_rn(piv) : 0.0f;
                    float f = (active & (1u << lane)) ? (r[k] * invp) : 0.0f;
                    #pragma unroll
                    for (int j = k + 1; j < NFD; j++) {
                        float pv = __shfl_sync(FULL, r[j], pp);
                        r[j] = fmaf(-f, pv, r[j]);
                    }
                }
                if (inv_cnt & 1) dfb = -dfb;
                if (half == t) det = dfb;
            }
        }

        if (l == 0)
            out[s0 + half] = det;
    }
}

extern "C" void kernel_launch(void* const* d_in, const int* in_sizes, int n_in,
                              void* d_out, int out_size)
{
    const int*   n_ptr = (const int*)d_in[0];      // n:   (B, 128) int32
    const float* Phi   = (const float*)d_in[1];    // Phi: (32, 128) float32
    float*       out   = (float*)d_out;            // det: (B,) float32

    int nsamples = in_sizes[0] / NOD;              // B = 131072 (even)

    // 148 SMs x 2 resident blocks (reg-heavy: 64-reg matrix per thread).
    int grid = 148 * 2;
    slater_det_kernel<<<grid, BT>>>(n_ptr, Phi, out, nsamples);
}